// round 17
// baseline (speedup 1.0000x reference)
#include <cuda_runtime.h>

// HarmonicOscillator — confirmed numerics (rel_err 2.6e-7):
//   v = f0_up * fl32(1/22050); interp = two muls + add (no contraction);
//   cumsum = XLA ReduceWindowRewriter(base=16), serial 16-folds per tile,
//   levels 262144->16384->1024->64->4 (terminal serial), combine
//   out = fl(outer_excl + inner), row 0 exact.
// R17: k_main = 8 samples/thread (1024-sample blocks, 3 staged amp groups,
//      q-loop unroll 4 + exact add2 harmonic recurrence for I$ fit).

#define BATCH 8
#define FRAMES 512
#define NH 64
#define NS 262144              // 512*512
#define ROWS 16384             // NS/16

__device__ float g_P0[BATCH][NS];
__device__ float g_P1[BATCH][ROWS];
__device__ float g_T2[BATCH][1024];
__device__ float g_S2[BATCH][1024];

typedef unsigned long long u64;

__device__ __forceinline__ u64 pk(float lo, float hi) {
    u64 r; asm("mov.b64 %0,{%1,%2};" : "=l"(r) : "f"(lo), "f"(hi)); return r;
}
__device__ __forceinline__ void upk(u64 v, float& lo, float& hi) {
    asm("mov.b64 {%0,%1},%2;" : "=f"(lo), "=f"(hi) : "l"(v));
}
__device__ __forceinline__ u64 fma2(u64 a, u64 b, u64 c) {
    u64 d; asm("fma.rn.f32x2 %0,%1,%2,%3;" : "=l"(d) : "l"(a), "l"(b), "l"(c)); return d;
}
__device__ __forceinline__ u64 mul2(u64 a, u64 b) {
    u64 d; asm("mul.rn.f32x2 %0,%1,%2;" : "=l"(d) : "l"(a), "l"(b)); return d;
}
__device__ __forceinline__ u64 add2(u64 a, u64 b) {
    u64 d; asm("add.rn.f32x2 %0,%1,%2;" : "=l"(d) : "l"(a), "l"(b)); return d;
}
__device__ __forceinline__ u64 sub2(u64 a, u64 b) {
    u64 d; asm("sub.rn.f32x2 %0,%1,%2;" : "=l"(d) : "l"(a), "l"(b)); return d;
}

__device__ __forceinline__ float interp_c() {
    return (float)(511.0 / 262143.0);
}

// ---- k1: P0 tile prefixes + P1 level-1 prefixes + T2 tile sums ----
__global__ void __launch_bounds__(256) k1(const float* __restrict__ f0) {
    const int b = blockIdx.y;
    const int t = threadIdx.x;                  // 0..255
    const int row = blockIdx.x * 256 + t;
    const float* fr = f0 + b * FRAMES;

    const int base = row * 16;

    float posJ = __fmul_rn((float)base, interp_c());
    const int j = (int)floorf(posJ);
    const float v0 = __ldg(fr + j);
    const float v1 = __ldg(fr + min(j + 1, FRAMES - 1));
    const float v2 = __ldg(fr + min(j + 2, FRAMES - 1));

    float x[16];
    float acc = 0.0f;
    #pragma unroll
    for (int c = 0; c < 16; ++c) {
        const int n = base + c;
        float nf  = (float)n;
        float pos = __fmul_rn(nf, interp_c());
        float fi0 = floorf(pos);
        int   i0  = (int)fi0;
        int   i1  = min(i0 + 1, FRAMES - 1);
        float w   = __fadd_rn(pos, -fi0);
        float omw = __fadd_rn(1.0f, -w);
        float a  = (i0 == j)     ? v0 : v1;
        float cc = (i1 == j + 1) ? v1 : v2;
        float up  = __fadd_rn(__fmul_rn(a, omw), __fmul_rn(cc, w));
        const float RECIP_SR = (float)(1.0 / 22050.0);
        float v   = __fmul_rn(up, RECIP_SR);
        acc = __fadd_rn(acc, v);
        x[c] = acc;
    }
    float4* dst = (float4*)(g_P0[b] + base);
    dst[0] = make_float4(x[0],  x[1],  x[2],  x[3]);
    dst[1] = make_float4(x[4],  x[5],  x[6],  x[7]);
    dst[2] = make_float4(x[8],  x[9],  x[10], x[11]);
    dst[3] = make_float4(x[12], x[13], x[14], x[15]);

    __shared__ float sT1[256];
    __shared__ float sP1[256];
    sT1[t] = acc;
    __syncthreads();
    if (t < 16) {
        float a2 = 0.0f;
        #pragma unroll
        for (int c = 0; c < 16; ++c) {
            a2 = __fadd_rn(a2, sT1[t * 16 + c]);
            sP1[t * 16 + c] = a2;
        }
        g_T2[b][blockIdx.x * 16 + t] = a2;
    }
    __syncthreads();
    g_P1[b][row] = sP1[t];
}

// ---- k2: levels 2..4, emit scan2 (1024/batch) ----
__global__ void k2() {
    const int b = blockIdx.x;
    const int t = threadIdx.x;                  // 0..127
    __shared__ float sP2[1024];
    __shared__ float sS3[64];
    __shared__ float sP4[4];

    if (t < 64) {
        float a = 0.0f;
        #pragma unroll
        for (int c = 0; c < 16; ++c) {
            a = __fadd_rn(a, g_T2[b][t * 16 + c]);
            sP2[t * 16 + c] = a;
        }
    }
    __syncthreads();
    if (t < 4) {
        float a = 0.0f;
        #pragma unroll
        for (int c = 0; c < 16; ++c) {
            a = __fadd_rn(a, sP2[(t * 16 + c) * 16 + 15]);
            sS3[t * 16 + c] = a;
        }
    }
    __syncthreads();
    if (t == 0) {
        float a = 0.0f;
        #pragma unroll
        for (int c = 0; c < 4; ++c) {
            a = __fadd_rn(a, sS3[c * 16 + 15]);
            sP4[c] = a;
        }
    }
    __syncthreads();
    if (t < 48) {
        int m = t + 16;
        sS3[m] = __fadd_rn(sP4[(m >> 4) - 1], sS3[m]);
    }
    __syncthreads();
    #pragma unroll
    for (int k = 0; k < 8; ++k) {
        int jj = t + k * 128;
        float p2 = sP2[jj];
        g_S2[b][jj] = (jj < 16) ? p2 : __fadd_rn(sS3[(jj >> 4) - 1], p2);
    }
}

// ---- S reconstruction (exact reference fl nesting) ----
__device__ __forceinline__ float recon_S(int b, int n) {
    float p0 = g_P0[b][n];
    const int r1i = n >> 4;
    if (r1i == 0) return p0;
    const int j = r1i - 1;
    float p1 = g_P1[b][j];
    const int r2 = j >> 4;
    float s1 = (r2 == 0) ? p1 : __fadd_rn(g_S2[b][r2 - 1], p1);
    return __fadd_rn(s1, p0);
}

// ---- k_main: packed f32x2 synthesis, 8 samples/thread ----
__global__ void __launch_bounds__(128) k_main(const float* __restrict__ amps,
                                              float* __restrict__ out) {
    const int b = blockIdx.y;
    const int n0 = blockIdx.x * 1024;
    const int t = threadIdx.x;                   // 0..127

    float posF = __fmul_rn((float)n0, interp_c());
    const int i0f = (int)floorf(posF);

    // 1024 samples span < 2 frames -> i0 - i0f in {0,1,2}: 3 staged groups
    __shared__ __align__(16) u64 sA0[3][32];
    __shared__ __align__(16) u64 sDF[3][32];
    if (t < 96) {
        int g = t >> 5;                          // 0..2
        int s = t & 31;
        int r0 = min(i0f + g, FRAMES - 1);
        int r1 = min(r0 + 1, FRAMES - 1);
        const u64* rowA = (const u64*)(amps + ((size_t)b * FRAMES + r0) * NH);
        const u64* rowB = (const u64*)(amps + ((size_t)b * FRAMES + r1) * NH);
        u64 a0 = __ldg(rowA + s);
        u64 a1 = __ldg(rowB + s);
        sA0[g][s] = a0;
        sDF[g][s] = sub2(a1, a0);
    }

    const float TWO_PI_F = 6.283185307179586f;

    int gS[8];
    u64 w2[8], ph2[8];
    #pragma unroll
    for (int s = 0; s < 8; ++s) {
        const int n = n0 + t + s * 128;
        float ph = __fmul_rn(recon_S(b, n), TWO_PI_F);
        float pos = __fmul_rn((float)n, interp_c());
        float fi  = floorf(pos);
        int   i0  = (int)fi;
        float w   = __fadd_rn(pos, -fi);
        gS[s]  = i0 - i0f;                       // 0..2
        w2[s]  = pk(w, w);
        ph2[s] = pk(ph, ph);
    }

    __syncthreads();

    const float INV2PI = (float)(1.0 / 6.283185307179586);
    const float C1 = 6.283185482025146484375f;
    const float C2 = -1.7484556e-7f;
    const float MAGIC = 12582912.0f;             // 1.5 * 2^23

    u64 IV2 = pk(INV2PI, INV2PI);
    u64 MG2 = pk(MAGIC, MAGIC);
    u64 C1n = pk(-C1, -C1);
    u64 C2n = pk(-C2, -C2);
    u64 FOUR = pk(4.0f, 4.0f);
    u64 h0 = pk(1.0f, 2.0f);
    u64 h1 = pk(3.0f, 4.0f);
    u64 acc0[8], acc1[8];
    #pragma unroll
    for (int s = 0; s < 8; ++s) { acc0[s] = pk(0.0f, 0.0f); acc1[s] = pk(0.0f, 0.0f); }

    #pragma unroll 4
    for (int q = 0; q < NH / 4; ++q) {
        #pragma unroll
        for (int s = 0; s < 8; ++s) {
            ulonglong2 a0v = ((const ulonglong2*)sA0[gS[s]])[q];
            ulonglong2 dfv = ((const ulonglong2*)sDF[gS[s]])[q];
            u64 amp0 = fma2(w2[s], dfv.x, a0v.x);
            u64 amp1 = fma2(w2[s], dfv.y, a0v.y);

            {   u64 pr = mul2(ph2[s], h0);
                u64 tt = fma2(pr, IV2, MG2);
                u64 kf = sub2(tt, MG2);
                u64 r  = fma2(kf, C1n, pr);
                r      = fma2(kf, C2n, r);
                float rl, rh; upk(r, rl, rh);
                acc0[s] = fma2(pk(__sinf(rl), __sinf(rh)), amp0, acc0[s]);
            }
            {   u64 pr = mul2(ph2[s], h1);
                u64 tt = fma2(pr, IV2, MG2);
                u64 kf = sub2(tt, MG2);
                u64 r  = fma2(kf, C1n, pr);
                r      = fma2(kf, C2n, r);
                float rl, rh; upk(r, rl, rh);
                acc1[s] = fma2(pk(__sinf(rl), __sinf(rh)), amp1, acc1[s]);
            }
        }
        h0 = add2(h0, FOUR);                     // exact integer steps in f32
        h1 = add2(h1, FOUR);
    }
    #pragma unroll
    for (int s = 0; s < 8; ++s) {
        float a0l, a0h, a1l, a1h;
        upk(acc0[s], a0l, a0h);
        upk(acc1[s], a1l, a1h);
        out[(size_t)b * NS + n0 + t + s * 128] = (a0l + a0h) + (a1l + a1h);
    }
}

extern "C" void kernel_launch(void* const* d_in, const int* in_sizes, int n_in,
                              void* d_out, int out_size) {
    const float* f0   = (const float*)d_in[0];   // (8, 512)
    const float* amps = (const float*)d_in[1];   // (8, 512, 64)
    float* out = (float*)d_out;                  // (8, 262144)

    k1<<<dim3(ROWS / 256, BATCH), 256>>>(f0);
    k2<<<BATCH, 128>>>();
    k_main<<<dim3(NS / 1024, BATCH), 128>>>(amps, out);
}